// round 2
// baseline (speedup 1.0000x reference)
#include <cuda_runtime.h>

#define DD 64
#define MAXN 100000

// Scratch (allocation-free rule: __device__ globals)
__device__ float g_P[MAXN * DD];     // relu(X @ Vp + Bm) per node
__device__ float g_G[MAXN * DD];     // X @ Vg per node
__device__ float g_den[MAXN * DD];   // softmax denominator accumulator

// ---------------------------------------------------------------------------
// Init: zero d_out (numerator) and g_den in one kernel.
// ---------------------------------------------------------------------------
__global__ void __launch_bounds__(256) init_kernel(
    float4* __restrict__ out, float4* __restrict__ den, int n4)
{
    const int i = blockIdx.x * blockDim.x + threadIdx.x;
    if (i < n4) {
        const float4 z = make_float4(0.f, 0.f, 0.f, 0.f);
        out[i] = z;
        den[i] = z;
    }
}

// ---------------------------------------------------------------------------
// Node kernel: P = relu(X @ Vp + Bm), G = X @ Vg   (per-node, hoisted GEMMs)
// Block = 256 threads, 32 nodes per block. V matrices staged in smem.
// Lane l owns output dims {l, l+32}; each warp computes 4 nodes (16 accums).
// ---------------------------------------------------------------------------
__global__ void __launch_bounds__(256) node_kernel(
    const float* __restrict__ X,
    const float* __restrict__ Vp,
    const float* __restrict__ Vg,
    const float* __restrict__ Bm,
    int N)
{
    __shared__ float sVp[DD * DD];
    __shared__ float sVg[DD * DD];
    __shared__ float sX[32 * DD];

    const int tid = threadIdx.x;

    // Stage weight matrices (row-major [k][d], identical layout)
    for (int i = tid; i < DD * DD / 4; i += blockDim.x) {
        ((float4*)sVp)[i] = ((const float4*)Vp)[i];
        ((float4*)sVg)[i] = ((const float4*)Vg)[i];
    }

    const int tile = blockIdx.x * 32;
    // Stage 32-node X tile
    for (int i = tid; i < 32 * DD / 4; i += blockDim.x) {
        int row = i >> 4;
        int grow = tile + row;
        float4 v = make_float4(0.f, 0.f, 0.f, 0.f);
        if (grow < N) v = ((const float4*)X)[grow * 16 + (i & 15)];
        ((float4*)sX)[i] = v;
    }
    __syncthreads();

    const int w = tid >> 5;       // warp id: 0..7
    const int l = tid & 31;       // lane
    const int nb = w * 4;         // local node base (4 nodes per warp)

    float ap0[4] = {0.f, 0.f, 0.f, 0.f};
    float ap1[4] = {0.f, 0.f, 0.f, 0.f};
    float ag0[4] = {0.f, 0.f, 0.f, 0.f};
    float ag1[4] = {0.f, 0.f, 0.f, 0.f};

    #pragma unroll
    for (int k4 = 0; k4 < 16; k4++) {
        float4 xv[4];
        #pragma unroll
        for (int n = 0; n < 4; n++)
            xv[n] = ((const float4*)sX)[(nb + n) * 16 + k4];   // warp broadcast
        #pragma unroll
        for (int kk = 0; kk < 4; kk++) {
            const int k = k4 * 4 + kk;
            const float vp0 = sVp[k * DD + l];
            const float vp1 = sVp[k * DD + 32 + l];
            const float vg0 = sVg[k * DD + l];
            const float vg1 = sVg[k * DD + 32 + l];
            #pragma unroll
            for (int n = 0; n < 4; n++) {
                const float x = (kk == 0) ? xv[n].x : (kk == 1) ? xv[n].y
                              : (kk == 2) ? xv[n].z : xv[n].w;
                ap0[n] += x * vp0;
                ap1[n] += x * vp1;
                ag0[n] += x * vg0;
                ag1[n] += x * vg1;
            }
        }
    }

    const float bm0 = Bm[l];
    const float bm1 = Bm[32 + l];
    #pragma unroll
    for (int n = 0; n < 4; n++) {
        const int grow = tile + nb + n;
        if (grow < N) {
            g_P[grow * DD + l]      = fmaxf(ap0[n] + bm0, 0.f);
            g_P[grow * DD + 32 + l] = fmaxf(ap1[n] + bm1, 0.f);
            g_G[grow * DD + l]      = ag0[n];
            g_G[grow * DD + 32 + l] = ag1[n];
        }
    }
}

// ---------------------------------------------------------------------------
// Edge kernel: per edge e, ex = exp(G[s] + Eg[t] + Bg)
//   den[r] += ex ;  num[r] += P[s] * ex     (float4 vector atomics)
// 16 lanes per edge -> each gather/atomic is one contiguous 256B burst.
// The per-receiver softmax max-subtraction cancels exactly; energies are
// bounded (|en| < ~10), so raw exp in fp32 is safe.
// ---------------------------------------------------------------------------
__global__ void __launch_bounds__(256) edge_kernel(
    const float* __restrict__ Eg,
    const float* __restrict__ Bg,
    const int*   __restrict__ snd,
    const int*   __restrict__ rcv,
    const int*   __restrict__ typ,
    float4*      __restrict__ num,    // = d_out viewed as float4
    float4*      __restrict__ dn4,
    int E)
{
    const int gt = blockIdx.x * blockDim.x + threadIdx.x;
    const int e  = gt >> 4;
    const int li = gt & 15;
    if (e >= E) return;

    const int s = __ldg(&snd[e]);
    const int r = __ldg(&rcv[e]);
    const int t = __ldg(&typ[e]);

    const float4* G4 = (const float4*)g_G;
    const float4* P4 = (const float4*)g_P;

    const float4 g  = G4[s * 16 + li];
    const float4 eg = ((const float4*)Eg)[t * 16 + li];
    const float4 bg = ((const float4*)Bg)[li];

    float4 ex;
    ex.x = __expf(g.x + eg.x + bg.x);
    ex.y = __expf(g.y + eg.y + bg.y);
    ex.z = __expf(g.z + eg.z + bg.z);
    ex.w = __expf(g.w + eg.w + bg.w);

    atomicAdd(&dn4[r * 16 + li], ex);

    const float4 p = P4[s * 16 + li];
    float4 m;
    m.x = p.x * ex.x;
    m.y = p.y * ex.y;
    m.z = p.z * ex.z;
    m.w = p.w * ex.w;
    atomicAdd(&num[r * 16 + li], m);
}

// ---------------------------------------------------------------------------
// Finalize: out = num / den  (0 where den == 0, i.e. receivers with no edges)
// ---------------------------------------------------------------------------
__global__ void __launch_bounds__(256) finalize_kernel(
    float4* __restrict__ out, const float4* __restrict__ dn4, int n4)
{
    const int i = blockIdx.x * blockDim.x + threadIdx.x;
    if (i >= n4) return;
    float4 v  = out[i];
    const float4 dn = dn4[i];
    v.x = (dn.x > 0.f) ? v.x / dn.x : 0.f;
    v.y = (dn.y > 0.f) ? v.y / dn.y : 0.f;
    v.z = (dn.z > 0.f) ? v.z / dn.z : 0.f;
    v.w = (dn.w > 0.f) ? v.w / dn.w : 0.f;
    out[i] = v;
}

extern "C" void kernel_launch(void* const* d_in, const int* in_sizes, int n_in,
                              void* d_out, int out_size)
{
    const float* node_codes = (const float*)d_in[0];
    const float* Vp         = (const float*)d_in[1];
    const float* Vg         = (const float*)d_in[2];
    const float* Eg         = (const float*)d_in[3];
    const float* Bm         = (const float*)d_in[4];
    const float* Bg         = (const float*)d_in[5];
    const int*   snd        = (const int*)d_in[6];
    const int*   rcv        = (const int*)d_in[7];
    const int*   typ        = (const int*)d_in[8];

    const int N = in_sizes[0] / DD;
    const int E = in_sizes[6];

    void* denp = nullptr;
    cudaGetSymbolAddress(&denp, g_den);
    float4* dn4 = (float4*)denp;

    const int n4 = N * (DD / 4);

    init_kernel<<<(n4 + 255) / 256, 256>>>((float4*)d_out, dn4, n4);

    node_kernel<<<(N + 31) / 32, 256>>>(node_codes, Vp, Vg, Bm, N);

    {
        const long long threads = (long long)E * 16;
        const int blocks = (int)((threads + 255) / 256);
        edge_kernel<<<blocks, 256>>>(Eg, Bg, snd, rcv, typ,
                                     (float4*)d_out, dn4, E);
    }

    finalize_kernel<<<(n4 + 255) / 256, 256>>>((float4*)d_out, dn4, n4);
}

// round 3
// speedup vs baseline: 1.2119x; 1.2119x over previous
#include <cuda_runtime.h>

#define DD   64
#define MAXN 100000
#define MAXE 1600000
#define NREL 201

// Scratch (allocation-free rule: __device__ globals)
__device__ float g_P[MAXN * DD];       // relu(X @ Vp + Bm) per node
__device__ float g_G[MAXN * DD];       // X @ Vg per node
__device__ float g_Egb[NREL * DD];     // E_gate + B_gate_pre (prefolded)
__device__ int   g_cnt[MAXN];          // per-receiver edge count
__device__ int   g_incl[MAXN];         // inclusive scan within scan-blocks
__device__ int   g_btot[128];          // per-scan-block totals
__device__ int   g_boff[128];          // exclusive scan of block totals
__device__ int   g_start[MAXN];        // CSR row start (exclusive scan)
__device__ int   g_cur[MAXN];          // scatter cursor
__device__ int   g_esnd[MAXE];         // sender idx, grouped by receiver
__device__ int   g_etyp[MAXE];         // type idx, grouped by receiver

// ---------------------------------------------------------------------------
// Prep: zero histogram counters; prefold Egb = E_gate + B_gate_pre.
// ---------------------------------------------------------------------------
__global__ void __launch_bounds__(256) prep_kernel(
    const float* __restrict__ Eg, const float* __restrict__ Bg, int N)
{
    const int i = blockIdx.x * blockDim.x + threadIdx.x;
    if (i < N) g_cnt[i] = 0;
    if (i < NREL * DD) g_Egb[i] = Eg[i] + Bg[i & (DD - 1)];
}

// ---------------------------------------------------------------------------
// Node kernel: P = relu(X @ Vp + Bm), G = X @ Vg   (per-node, hoisted GEMMs)
// ---------------------------------------------------------------------------
__global__ void __launch_bounds__(256) node_kernel(
    const float* __restrict__ X,
    const float* __restrict__ Vp,
    const float* __restrict__ Vg,
    const float* __restrict__ Bm,
    int N)
{
    __shared__ float sVp[DD * DD];
    __shared__ float sVg[DD * DD];
    __shared__ float sX[32 * DD];

    const int tid = threadIdx.x;

    for (int i = tid; i < DD * DD / 4; i += blockDim.x) {
        ((float4*)sVp)[i] = ((const float4*)Vp)[i];
        ((float4*)sVg)[i] = ((const float4*)Vg)[i];
    }

    const int tile = blockIdx.x * 32;
    for (int i = tid; i < 32 * DD / 4; i += blockDim.x) {
        int row = i >> 4;
        int grow = tile + row;
        float4 v = make_float4(0.f, 0.f, 0.f, 0.f);
        if (grow < N) v = ((const float4*)X)[grow * 16 + (i & 15)];
        ((float4*)sX)[i] = v;
    }
    __syncthreads();

    const int w = tid >> 5;
    const int l = tid & 31;
    const int nb = w * 4;

    float ap0[4] = {0.f, 0.f, 0.f, 0.f};
    float ap1[4] = {0.f, 0.f, 0.f, 0.f};
    float ag0[4] = {0.f, 0.f, 0.f, 0.f};
    float ag1[4] = {0.f, 0.f, 0.f, 0.f};

    #pragma unroll
    for (int k4 = 0; k4 < 16; k4++) {
        float4 xv[4];
        #pragma unroll
        for (int n = 0; n < 4; n++)
            xv[n] = ((const float4*)sX)[(nb + n) * 16 + k4];
        #pragma unroll
        for (int kk = 0; kk < 4; kk++) {
            const int k = k4 * 4 + kk;
            const float vp0 = sVp[k * DD + l];
            const float vp1 = sVp[k * DD + 32 + l];
            const float vg0 = sVg[k * DD + l];
            const float vg1 = sVg[k * DD + 32 + l];
            #pragma unroll
            for (int n = 0; n < 4; n++) {
                const float x = (kk == 0) ? xv[n].x : (kk == 1) ? xv[n].y
                              : (kk == 2) ? xv[n].z : xv[n].w;
                ap0[n] += x * vp0;
                ap1[n] += x * vp1;
                ag0[n] += x * vg0;
                ag1[n] += x * vg1;
            }
        }
    }

    const float bm0 = Bm[l];
    const float bm1 = Bm[32 + l];
    #pragma unroll
    for (int n = 0; n < 4; n++) {
        const int grow = tile + nb + n;
        if (grow < N) {
            g_P[grow * DD + l]      = fmaxf(ap0[n] + bm0, 0.f);
            g_P[grow * DD + 32 + l] = fmaxf(ap1[n] + bm1, 0.f);
            g_G[grow * DD + l]      = ag0[n];
            g_G[grow * DD + 32 + l] = ag1[n];
        }
    }
}

// ---------------------------------------------------------------------------
// CSR build: histogram -> two-level scan -> scatter (grouped by receiver)
// ---------------------------------------------------------------------------
__global__ void __launch_bounds__(256) hist_kernel(const int* __restrict__ rcv, int E)
{
    const int e = blockIdx.x * blockDim.x + threadIdx.x;
    if (e < E) atomicAdd(&g_cnt[rcv[e]], 1);
}

__global__ void __launch_bounds__(1024) scan1_kernel(int N)
{
    __shared__ int sm[1024];
    const int i = blockIdx.x * 1024 + threadIdx.x;
    int v = (i < N) ? g_cnt[i] : 0;
    sm[threadIdx.x] = v;
    __syncthreads();
    #pragma unroll
    for (int d = 1; d < 1024; d <<= 1) {
        int t = (threadIdx.x >= d) ? sm[threadIdx.x - d] : 0;
        __syncthreads();
        sm[threadIdx.x] += t;
        __syncthreads();
    }
    if (i < N) g_incl[i] = sm[threadIdx.x];
    if (threadIdx.x == 1023) g_btot[blockIdx.x] = sm[1023];
}

__global__ void __launch_bounds__(128) scan2_kernel(int nblk)
{
    __shared__ int sm[128];
    int v = (threadIdx.x < nblk) ? g_btot[threadIdx.x] : 0;
    sm[threadIdx.x] = v;
    __syncthreads();
    #pragma unroll
    for (int d = 1; d < 128; d <<= 1) {
        int t = (threadIdx.x >= d) ? sm[threadIdx.x - d] : 0;
        __syncthreads();
        sm[threadIdx.x] += t;
        __syncthreads();
    }
    if (threadIdx.x < nblk)
        g_boff[threadIdx.x] = (threadIdx.x == 0) ? 0 : sm[threadIdx.x - 1];
}

__global__ void __launch_bounds__(256) scan3_kernel(int N)
{
    const int i = blockIdx.x * blockDim.x + threadIdx.x;
    if (i < N) {
        const int start = g_incl[i] - g_cnt[i] + g_boff[i >> 10];
        g_start[i] = start;
        g_cur[i]   = start;
    }
}

__global__ void __launch_bounds__(256) scatter_kernel(
    const int* __restrict__ snd, const int* __restrict__ rcv,
    const int* __restrict__ typ, int E)
{
    const int e = blockIdx.x * blockDim.x + threadIdx.x;
    if (e < E) {
        const int r = rcv[e];
        const int pos = atomicAdd(&g_cur[r], 1);
        g_esnd[pos] = snd[e];
        g_etyp[pos] = typ[e];
    }
}

// ---------------------------------------------------------------------------
// Consume: one warp per receiver. Two half-warps process alternate edges;
// each half-warp's 16 lanes cover D=64 as float4. Accumulate num/den in
// registers, combine halves via shfl, write the output row once. No atomics.
// ---------------------------------------------------------------------------
__global__ void __launch_bounds__(256) consume_kernel(float4* __restrict__ out, int N)
{
    const int gw = (blockIdx.x * blockDim.x + threadIdx.x) >> 5;  // receiver
    if (gw >= N) return;
    const int lane = threadIdx.x & 31;
    const int half = lane >> 4;
    const int li   = lane & 15;

    const int start = g_start[gw];
    const int end   = start + g_cnt[gw];

    const float4* G4  = (const float4*)g_G;
    const float4* P4  = (const float4*)g_P;
    const float4* Eg4 = (const float4*)g_Egb;

    float4 num = make_float4(0.f, 0.f, 0.f, 0.f);
    float4 den = make_float4(0.f, 0.f, 0.f, 0.f);

    for (int i = start + half; i < end; i += 2) {
        const int s = g_esnd[i];
        const int t = g_etyp[i];
        const float4 g  = G4[s * 16 + li];
        const float4 eg = Eg4[t * 16 + li];
        float4 ex;
        ex.x = __expf(g.x + eg.x);
        ex.y = __expf(g.y + eg.y);
        ex.z = __expf(g.z + eg.z);
        ex.w = __expf(g.w + eg.w);
        den.x += ex.x; den.y += ex.y; den.z += ex.z; den.w += ex.w;
        const float4 p = P4[s * 16 + li];
        num.x += p.x * ex.x;
        num.y += p.y * ex.y;
        num.z += p.z * ex.z;
        num.w += p.w * ex.w;
    }

    // combine the two half-warps (same li, half 0 <-> half 1)
    num.x += __shfl_xor_sync(0xffffffffu, num.x, 16);
    num.y += __shfl_xor_sync(0xffffffffu, num.y, 16);
    num.z += __shfl_xor_sync(0xffffffffu, num.z, 16);
    num.w += __shfl_xor_sync(0xffffffffu, num.w, 16);
    den.x += __shfl_xor_sync(0xffffffffu, den.x, 16);
    den.y += __shfl_xor_sync(0xffffffffu, den.y, 16);
    den.z += __shfl_xor_sync(0xffffffffu, den.z, 16);
    den.w += __shfl_xor_sync(0xffffffffu, den.w, 16);

    if (half == 0) {
        float4 v;
        v.x = (den.x > 0.f) ? num.x / den.x : 0.f;
        v.y = (den.y > 0.f) ? num.y / den.y : 0.f;
        v.z = (den.z > 0.f) ? num.z / den.z : 0.f;
        v.w = (den.w > 0.f) ? num.w / den.w : 0.f;
        out[gw * 16 + li] = v;
    }
}

extern "C" void kernel_launch(void* const* d_in, const int* in_sizes, int n_in,
                              void* d_out, int out_size)
{
    const float* node_codes = (const float*)d_in[0];
    const float* Vp         = (const float*)d_in[1];
    const float* Vg         = (const float*)d_in[2];
    const float* Eg         = (const float*)d_in[3];
    const float* Bm         = (const float*)d_in[4];
    const float* Bg         = (const float*)d_in[5];
    const int*   snd        = (const int*)d_in[6];
    const int*   rcv        = (const int*)d_in[7];
    const int*   typ        = (const int*)d_in[8];

    const int N = in_sizes[0] / DD;
    const int E = in_sizes[6];

    const int prep_n = (N > NREL * DD) ? N : NREL * DD;
    prep_kernel<<<(prep_n + 255) / 256, 256>>>(Eg, Bg, N);

    node_kernel<<<(N + 31) / 32, 256>>>(node_codes, Vp, Vg, Bm, N);

    hist_kernel<<<(E + 255) / 256, 256>>>(rcv, E);

    const int nblk = (N + 1023) / 1024;
    scan1_kernel<<<nblk, 1024>>>(N);
    scan2_kernel<<<1, 128>>>(nblk);
    scan3_kernel<<<(N + 255) / 256, 256>>>(N);

    scatter_kernel<<<(E + 255) / 256, 256>>>(snd, rcv, typ, E);

    {
        const long long threads = (long long)N * 32;
        const int blocks = (int)((threads + 255) / 256);
        consume_kernel<<<blocks, 256>>>((float4*)d_out, N);
    }
}

// round 4
// speedup vs baseline: 1.5187x; 1.2531x over previous
#include <cuda_runtime.h>
#include <cuda_fp16.h>

#define DD   64
#define MAXN 100000
#define MAXE 1600000
#define NREL 201

// Scratch (allocation-free rule: __device__ globals)
// g_EP: per node, 128 halves = [expG(64) | P(64)]  -> one 256B row
__device__ __half g_EP[MAXN * 128];
__device__ float  g_expEgb[NREL * DD];   // exp(E_gate + B_gate_pre)
__device__ int    g_cnt[MAXN];
__device__ int    g_incl[MAXN];
__device__ int    g_btot[128];
__device__ int    g_boff[128];
__device__ int    g_start[MAXN];
__device__ int    g_cur[MAXN];
__device__ int2   g_edge[MAXE];          // (sender, type), grouped by receiver

// ---------------------------------------------------------------------------
// Prep: zero histogram; expEgb = exp(E_gate + B_gate_pre)
// ---------------------------------------------------------------------------
__global__ void __launch_bounds__(256) prep_kernel(
    const float* __restrict__ Eg, const float* __restrict__ Bg, int N)
{
    const int i = blockIdx.x * blockDim.x + threadIdx.x;
    if (i < N) g_cnt[i] = 0;
    if (i < NREL * DD) g_expEgb[i] = __expf(Eg[i] + Bg[i & (DD - 1)]);
}

// ---------------------------------------------------------------------------
// Node kernel: expG = exp(X @ Vg), P = relu(X @ Vp + Bm); stored fp16,
// interleaved [expG | P] per node.
// ---------------------------------------------------------------------------
__global__ void __launch_bounds__(256) node_kernel(
    const float* __restrict__ X,
    const float* __restrict__ Vp,
    const float* __restrict__ Vg,
    const float* __restrict__ Bm,
    int N)
{
    __shared__ float sVp[DD * DD];
    __shared__ float sVg[DD * DD];
    __shared__ float sX[32 * DD];

    const int tid = threadIdx.x;

    for (int i = tid; i < DD * DD / 4; i += blockDim.x) {
        ((float4*)sVp)[i] = ((const float4*)Vp)[i];
        ((float4*)sVg)[i] = ((const float4*)Vg)[i];
    }

    const int tile = blockIdx.x * 32;
    for (int i = tid; i < 32 * DD / 4; i += blockDim.x) {
        int row = i >> 4;
        int grow = tile + row;
        float4 v = make_float4(0.f, 0.f, 0.f, 0.f);
        if (grow < N) v = ((const float4*)X)[grow * 16 + (i & 15)];
        ((float4*)sX)[i] = v;
    }
    __syncthreads();

    const int w = tid >> 5;
    const int l = tid & 31;
    const int nb = w * 4;

    float ap0[4] = {0.f, 0.f, 0.f, 0.f};
    float ap1[4] = {0.f, 0.f, 0.f, 0.f};
    float ag0[4] = {0.f, 0.f, 0.f, 0.f};
    float ag1[4] = {0.f, 0.f, 0.f, 0.f};

    #pragma unroll
    for (int k4 = 0; k4 < 16; k4++) {
        float4 xv[4];
        #pragma unroll
        for (int n = 0; n < 4; n++)
            xv[n] = ((const float4*)sX)[(nb + n) * 16 + k4];
        #pragma unroll
        for (int kk = 0; kk < 4; kk++) {
            const int k = k4 * 4 + kk;
            const float vp0 = sVp[k * DD + l];
            const float vp1 = sVp[k * DD + 32 + l];
            const float vg0 = sVg[k * DD + l];
            const float vg1 = sVg[k * DD + 32 + l];
            #pragma unroll
            for (int n = 0; n < 4; n++) {
                const float x = (kk == 0) ? xv[n].x : (kk == 1) ? xv[n].y
                              : (kk == 2) ? xv[n].z : xv[n].w;
                ap0[n] += x * vp0;
                ap1[n] += x * vp1;
                ag0[n] += x * vg0;
                ag1[n] += x * vg1;
            }
        }
    }

    const float bm0 = Bm[l];
    const float bm1 = Bm[32 + l];
    #pragma unroll
    for (int n = 0; n < 4; n++) {
        const int grow = tile + nb + n;
        if (grow < N) {
            __half* row = &g_EP[grow * 128];
            row[l]           = __float2half_rn(__expf(ag0[n]));       // expG
            row[32 + l]      = __float2half_rn(__expf(ag1[n]));
            row[64 + l]      = __float2half_rn(fmaxf(ap0[n] + bm0, 0.f));  // P
            row[96 + l]      = __float2half_rn(fmaxf(ap1[n] + bm1, 0.f));
        }
    }
}

// ---------------------------------------------------------------------------
// CSR build: histogram -> two-level scan -> scatter (grouped by receiver)
// ---------------------------------------------------------------------------
__global__ void __launch_bounds__(256) hist_kernel(const int* __restrict__ rcv, int E)
{
    const int e = blockIdx.x * blockDim.x + threadIdx.x;
    if (e < E) atomicAdd(&g_cnt[rcv[e]], 1);
}

__global__ void __launch_bounds__(1024) scan1_kernel(int N)
{
    __shared__ int sm[1024];
    const int i = blockIdx.x * 1024 + threadIdx.x;
    int v = (i < N) ? g_cnt[i] : 0;
    sm[threadIdx.x] = v;
    __syncthreads();
    #pragma unroll
    for (int d = 1; d < 1024; d <<= 1) {
        int t = (threadIdx.x >= d) ? sm[threadIdx.x - d] : 0;
        __syncthreads();
        sm[threadIdx.x] += t;
        __syncthreads();
    }
    if (i < N) g_incl[i] = sm[threadIdx.x];
    if (threadIdx.x == 1023) g_btot[blockIdx.x] = sm[1023];
}

__global__ void __launch_bounds__(128) scan2_kernel(int nblk)
{
    __shared__ int sm[128];
    int v = (threadIdx.x < nblk) ? g_btot[threadIdx.x] : 0;
    sm[threadIdx.x] = v;
    __syncthreads();
    #pragma unroll
    for (int d = 1; d < 128; d <<= 1) {
        int t = (threadIdx.x >= d) ? sm[threadIdx.x - d] : 0;
        __syncthreads();
        sm[threadIdx.x] += t;
        __syncthreads();
    }
    if (threadIdx.x < nblk)
        g_boff[threadIdx.x] = (threadIdx.x == 0) ? 0 : sm[threadIdx.x - 1];
}

__global__ void __launch_bounds__(256) scan3_kernel(int N)
{
    const int i = blockIdx.x * blockDim.x + threadIdx.x;
    if (i < N) {
        const int start = g_incl[i] - g_cnt[i] + g_boff[i >> 10];
        g_start[i] = start;
        g_cur[i]   = start;
    }
}

__global__ void __launch_bounds__(256) scatter_kernel(
    const int* __restrict__ snd, const int* __restrict__ rcv,
    const int* __restrict__ typ, int E)
{
    const int e = blockIdx.x * blockDim.x + threadIdx.x;
    if (e < E) {
        const int pos = atomicAdd(&g_cur[rcv[e]], 1);
        g_edge[pos] = make_int2(snd[e], typ[e]);
    }
}

// ---------------------------------------------------------------------------
// Consume: one warp per receiver. Half-warps take contiguous halves of the
// edge range; 16 lanes cover D=64 (4 dims/lane). No exp (prefactored), no
// atomics; 2-edge unroll for MLP. fp16 gathers (8B/lane), fp32 accumulate.
// ---------------------------------------------------------------------------
__device__ __forceinline__ void edge_accum(
    int2 e, int li, const uint2* __restrict__ EP2,
    const float4* __restrict__ Eg4, float4& num, float4& den)
{
    const uint2 gu = EP2[e.x * 32 + li];         // expG, 4 dims
    const uint2 pu = EP2[e.x * 32 + 16 + li];    // P, 4 dims
    const float4 eg = Eg4[e.y * 16 + li];        // exp(Eg+Bg), fp32 (hot)

    const float2 g01 = __half22float2(*(const __half2*)&gu.x);
    const float2 g23 = __half22float2(*(const __half2*)&gu.y);
    const float2 p01 = __half22float2(*(const __half2*)&pu.x);
    const float2 p23 = __half22float2(*(const __half2*)&pu.y);

    const float ex0 = g01.x * eg.x;
    const float ex1 = g01.y * eg.y;
    const float ex2 = g23.x * eg.z;
    const float ex3 = g23.y * eg.w;

    den.x += ex0; den.y += ex1; den.z += ex2; den.w += ex3;
    num.x += p01.x * ex0;
    num.y += p01.y * ex1;
    num.z += p23.x * ex2;
    num.w += p23.y * ex3;
}

__global__ void __launch_bounds__(256) consume_kernel(float4* __restrict__ out, int N)
{
    const int gw = (blockIdx.x * blockDim.x + threadIdx.x) >> 5;  // receiver
    if (gw >= N) return;
    const int lane = threadIdx.x & 31;
    const int half = lane >> 4;
    const int li   = lane & 15;

    const int start = g_start[gw];
    const int cnt   = g_cnt[gw];
    const int mid   = start + ((cnt + 1) >> 1);
    const int lo    = half ? mid : start;
    const int hi    = half ? (start + cnt) : mid;

    const uint2*  EP2 = (const uint2*)g_EP;
    const float4* Eg4 = (const float4*)g_expEgb;

    float4 num = make_float4(0.f, 0.f, 0.f, 0.f);
    float4 den = make_float4(0.f, 0.f, 0.f, 0.f);

    int i = lo;
    for (; i + 1 < hi; i += 2) {
        const int2 e0 = g_edge[i];
        const int2 e1 = g_edge[i + 1];
        edge_accum(e0, li, EP2, Eg4, num, den);
        edge_accum(e1, li, EP2, Eg4, num, den);
    }
    if (i < hi) {
        const int2 e0 = g_edge[i];
        edge_accum(e0, li, EP2, Eg4, num, den);
    }

    // combine the two half-warps (same li)
    num.x += __shfl_xor_sync(0xffffffffu, num.x, 16);
    num.y += __shfl_xor_sync(0xffffffffu, num.y, 16);
    num.z += __shfl_xor_sync(0xffffffffu, num.z, 16);
    num.w += __shfl_xor_sync(0xffffffffu, num.w, 16);
    den.x += __shfl_xor_sync(0xffffffffu, den.x, 16);
    den.y += __shfl_xor_sync(0xffffffffu, den.y, 16);
    den.z += __shfl_xor_sync(0xffffffffu, den.z, 16);
    den.w += __shfl_xor_sync(0xffffffffu, den.w, 16);

    if (half == 0) {
        float4 v;
        v.x = (den.x > 0.f) ? num.x / den.x : 0.f;
        v.y = (den.y > 0.f) ? num.y / den.y : 0.f;
        v.z = (den.z > 0.f) ? num.z / den.z : 0.f;
        v.w = (den.w > 0.f) ? num.w / den.w : 0.f;
        out[gw * 16 + li] = v;
    }
}

extern "C" void kernel_launch(void* const* d_in, const int* in_sizes, int n_in,
                              void* d_out, int out_size)
{
    const float* node_codes = (const float*)d_in[0];
    const float* Vp         = (const float*)d_in[1];
    const float* Vg         = (const float*)d_in[2];
    const float* Eg         = (const float*)d_in[3];
    const float* Bm         = (const float*)d_in[4];
    const float* Bg         = (const float*)d_in[5];
    const int*   snd        = (const int*)d_in[6];
    const int*   rcv        = (const int*)d_in[7];
    const int*   typ        = (const int*)d_in[8];

    const int N = in_sizes[0] / DD;
    const int E = in_sizes[6];

    const int prep_n = (N > NREL * DD) ? N : NREL * DD;
    prep_kernel<<<(prep_n + 255) / 256, 256>>>(Eg, Bg, N);

    node_kernel<<<(N + 31) / 32, 256>>>(node_codes, Vp, Vg, Bm, N);

    hist_kernel<<<(E + 255) / 256, 256>>>(rcv, E);

    const int nblk = (N + 1023) / 1024;
    scan1_kernel<<<nblk, 1024>>>(N);
    scan2_kernel<<<1, 128>>>(nblk);
    scan3_kernel<<<(N + 255) / 256, 256>>>(N);

    scatter_kernel<<<(E + 255) / 256, 256>>>(snd, rcv, typ, E);

    {
        const long long threads = (long long)N * 32;
        const int blocks = (int)((threads + 255) / 256);
        consume_kernel<<<blocks, 256>>>((float4*)d_out, N);
    }
}

// round 5
// speedup vs baseline: 1.5680x; 1.0325x over previous
#include <cuda_runtime.h>
#include <cuda_fp16.h>

#define DD   64
#define MAXN 100000
#define MAXE 1600000
#define NREL 201

// Scratch (allocation-free rule: __device__ globals)
// g_EP: per node, 128 halves = [expG(64) | P(64)]  -> one 256B row
__device__ __half    g_EP[MAXN * 128];
__device__ float     g_expEgb[NREL * DD];   // exp(E_gate + B_gate_pre)
__device__ int       g_cnt[MAXN];
__device__ int       g_incl[MAXN];
__device__ int       g_btot[128];
__device__ int       g_boff[128];
__device__ int       g_start[MAXN];
__device__ int       g_cur[MAXN];
__device__ unsigned  g_edge[MAXE];          // sender | (type<<17), grouped by receiver

// ---------------------------------------------------------------------------
// tf32 helpers
// ---------------------------------------------------------------------------
__device__ __forceinline__ unsigned f2tf32(float x) {
    unsigned r;
    asm("cvt.rna.tf32.f32 %0, %1;" : "=r"(r) : "f"(x));
    return r;
}

#define MMA_TF32(d0,d1,d2,d3,a0,a1,a2,a3,b0,b1) \
    asm volatile("mma.sync.aligned.m16n8k8.row.col.f32.tf32.tf32.f32 " \
        "{%0,%1,%2,%3}, {%4,%5,%6,%7}, {%8,%9}, {%0,%1,%2,%3};" \
        : "+f"(d0), "+f"(d1), "+f"(d2), "+f"(d3) \
        : "r"(a0), "r"(a1), "r"(a2), "r"(a3), "r"(b0), "r"(b1))

// ---------------------------------------------------------------------------
// Prep: zero histogram; expEgb = exp(E_gate + B_gate_pre)
// ---------------------------------------------------------------------------
__global__ void __launch_bounds__(256) prep_kernel(
    const float* __restrict__ Eg, const float* __restrict__ Bg, int N)
{
    const int i = blockIdx.x * blockDim.x + threadIdx.x;
    if (i < N) g_cnt[i] = 0;
    if (i < NREL * DD) g_expEgb[i] = __expf(Eg[i] + Bg[i & (DD - 1)]);
}

// ---------------------------------------------------------------------------
// Node kernel (tensor core): expG = exp(X @ Vg), P = relu(X @ Vp + Bm).
// mma.sync.m16n8k8 tf32 with 3-term split (hi*hi + hi*lo + lo*hi) for
// fp32-grade accuracy. One warp computes 16 nodes x 64 dims x 2 matrices.
// B (weight) fragments precomputed in fragment order into dynamic smem:
// layout sB[mat][n][k][hl][lane] of uint2 (b0,b1) -> conflict-free LDS.64.
// ---------------------------------------------------------------------------
__global__ void __launch_bounds__(256) node_kernel(
    const float* __restrict__ X,
    const float* __restrict__ Vp,
    const float* __restrict__ Vg,
    const float* __restrict__ Bm,
    int N)
{
    extern __shared__ unsigned sB[];   // 2*8*8*2*32 uint2 = 64KB
    const int tid = threadIdx.x;

    // Build weight fragments (mat0 = Vg -> expG cols, mat1 = Vp -> P cols)
    for (int idx = tid; idx < 2 * 8 * 8 * 2 * 32; idx += 256) {
        const int lane = idx & 31;
        const int hl   = (idx >> 5) & 1;
        const int k    = (idx >> 6) & 7;
        const int n    = (idx >> 9) & 7;
        const int mat  = (idx >> 12) & 1;
        const float* __restrict__ V = (mat == 0) ? Vg : Vp;
        const int t = lane & 3, g = lane >> 2;
        const float v0 = V[(k * 8 + t) * DD + n * 8 + g];
        const float v1 = V[(k * 8 + t + 4) * DD + n * 8 + g];
        unsigned o0, o1;
        if (hl == 0) {
            o0 = f2tf32(v0);
            o1 = f2tf32(v1);
        } else {
            const unsigned h0 = f2tf32(v0), h1 = f2tf32(v1);
            o0 = f2tf32(v0 - __uint_as_float(h0));
            o1 = f2tf32(v1 - __uint_as_float(h1));
        }
        ((uint2*)sB)[idx] = make_uint2(o0, o1);
    }
    __syncthreads();

    const int warp = tid >> 5;
    const int lane = tid & 31;
    const int m0   = (blockIdx.x * 8 + warp) * 16;
    if (m0 >= N) return;

    const int t = lane & 3, g = lane >> 2;
    const int r0 = m0 + g;
    const int r1 = m0 + g + 8;
    const bool r0ok = r0 < N;
    const bool r1ok = r1 < N;

    // A fragments for all 8 k-steps (hi + lo)
    unsigned Ahi[8][4], Alo[8][4];
    const float* __restrict__ xr0 = X + (size_t)r0 * DD;
    const float* __restrict__ xr1 = X + (size_t)r1 * DD;
    #pragma unroll
    for (int k = 0; k < 8; k++) {
        float x0 = r0ok ? __ldg(&xr0[k * 8 + t])     : 0.f;
        float x1 = r1ok ? __ldg(&xr1[k * 8 + t])     : 0.f;
        float x2 = r0ok ? __ldg(&xr0[k * 8 + t + 4]) : 0.f;
        float x3 = r1ok ? __ldg(&xr1[k * 8 + t + 4]) : 0.f;
        Ahi[k][0] = f2tf32(x0); Alo[k][0] = f2tf32(x0 - __uint_as_float(Ahi[k][0]));
        Ahi[k][1] = f2tf32(x1); Alo[k][1] = f2tf32(x1 - __uint_as_float(Ahi[k][1]));
        Ahi[k][2] = f2tf32(x2); Alo[k][2] = f2tf32(x2 - __uint_as_float(Ahi[k][2]));
        Ahi[k][3] = f2tf32(x3); Alo[k][3] = f2tf32(x3 - __uint_as_float(Ahi[k][3]));
    }

    const uint2* __restrict__ sB2 = (const uint2*)sB;

    #pragma unroll
    for (int mat = 0; mat < 2; mat++) {
        #pragma unroll
        for (int n = 0; n < 8; n++) {
            float d0 = 0.f, d1 = 0.f, d2 = 0.f, d3 = 0.f;
            #pragma unroll
            for (int k = 0; k < 8; k++) {
                const int base = (((mat * 8 + n) * 8 + k) * 2) * 32 + lane;
                const uint2 bh = sB2[base];
                const uint2 bl = sB2[base + 32];
                MMA_TF32(d0, d1, d2, d3,
                         Ahi[k][0], Ahi[k][1], Ahi[k][2], Ahi[k][3], bh.x, bh.y);
                MMA_TF32(d0, d1, d2, d3,
                         Ahi[k][0], Ahi[k][1], Ahi[k][2], Ahi[k][3], bl.x, bl.y);
                MMA_TF32(d0, d1, d2, d3,
                         Alo[k][0], Alo[k][1], Alo[k][2], Alo[k][3], bh.x, bh.y);
            }
            const int c0 = n * 8 + 2 * t;   // even column
            if (mat == 0) {
                // expG at cols [0,64)
                if (r0ok) *(__half2*)&g_EP[(size_t)r0 * 128 + c0] =
                    __floats2half2_rn(__expf(d0), __expf(d1));
                if (r1ok) *(__half2*)&g_EP[(size_t)r1 * 128 + c0] =
                    __floats2half2_rn(__expf(d2), __expf(d3));
            } else {
                // P at cols [64,128)
                const float b0v = __ldg(&Bm[c0]);
                const float b1v = __ldg(&Bm[c0 + 1]);
                if (r0ok) *(__half2*)&g_EP[(size_t)r0 * 128 + 64 + c0] =
                    __floats2half2_rn(fmaxf(d0 + b0v, 0.f), fmaxf(d1 + b1v, 0.f));
                if (r1ok) *(__half2*)&g_EP[(size_t)r1 * 128 + 64 + c0] =
                    __floats2half2_rn(fmaxf(d2 + b0v, 0.f), fmaxf(d3 + b1v, 0.f));
            }
        }
    }
}

// ---------------------------------------------------------------------------
// CSR build: histogram -> two-level scan -> scatter (grouped by receiver)
// ---------------------------------------------------------------------------
__global__ void __launch_bounds__(256) hist_kernel(const int* __restrict__ rcv, int E)
{
    const int e = blockIdx.x * blockDim.x + threadIdx.x;
    if (e < E) atomicAdd(&g_cnt[rcv[e]], 1);
}

__global__ void __launch_bounds__(1024) scan1_kernel(int N)
{
    __shared__ int wsum[32];
    const int i    = blockIdx.x * 1024 + threadIdx.x;
    const int lane = threadIdx.x & 31;
    const int w    = threadIdx.x >> 5;

    int s = (i < N) ? g_cnt[i] : 0;
    #pragma unroll
    for (int d = 1; d < 32; d <<= 1) {
        int tv = __shfl_up_sync(0xffffffffu, s, d);
        if (lane >= d) s += tv;
    }
    if (lane == 31) wsum[w] = s;
    __syncthreads();
    if (w == 0) {
        int ws = wsum[lane];
        #pragma unroll
        for (int d = 1; d < 32; d <<= 1) {
            int tv = __shfl_up_sync(0xffffffffu, ws, d);
            if (lane >= d) ws += tv;
        }
        wsum[lane] = ws;
    }
    __syncthreads();
    if (w > 0) s += wsum[w - 1];
    if (i < N) g_incl[i] = s;
    if (threadIdx.x == 1023) g_btot[blockIdx.x] = s;
}

__global__ void __launch_bounds__(128) scan2_kernel(int nblk)
{
    __shared__ int sm[128];
    int v = (threadIdx.x < nblk) ? g_btot[threadIdx.x] : 0;
    sm[threadIdx.x] = v;
    __syncthreads();
    #pragma unroll
    for (int d = 1; d < 128; d <<= 1) {
        int t = (threadIdx.x >= d) ? sm[threadIdx.x - d] : 0;
        __syncthreads();
        sm[threadIdx.x] += t;
        __syncthreads();
    }
    if (threadIdx.x < nblk)
        g_boff[threadIdx.x] = (threadIdx.x == 0) ? 0 : sm[threadIdx.x - 1];
}

__global__ void __launch_bounds__(256) scan3_kernel(int N)
{
    const int i = blockIdx.x * blockDim.x + threadIdx.x;
    if (i < N) {
        const int start = g_incl[i] - g_cnt[i] + g_boff[i >> 10];
        g_start[i] = start;
        g_cur[i]   = start;
    }
}

__global__ void __launch_bounds__(256) scatter_kernel(
    const int* __restrict__ snd, const int* __restrict__ rcv,
    const int* __restrict__ typ, int E)
{
    const int e = blockIdx.x * blockDim.x + threadIdx.x;
    if (e < E) {
        const int pos = atomicAdd(&g_cur[rcv[e]], 1);
        g_edge[pos] = (unsigned)snd[e] | ((unsigned)typ[e] << 17);
    }
}

// ---------------------------------------------------------------------------
// Consume: one warp per receiver. Half-warps take contiguous halves of the
// edge range; 16 lanes cover D=64 (4 dims/lane). No exp (prefactored), no
// atomics; 2-edge unroll for MLP. fp16 gathers, fp32 accumulate.
// ---------------------------------------------------------------------------
__device__ __forceinline__ void edge_accum(
    unsigned e, int li, const uint2* __restrict__ EP2,
    const float4* __restrict__ Eg4, float4& num, float4& den)
{
    const int s = (int)(e & 0x1FFFFu);
    const int t = (int)(e >> 17);

    const uint2 gu = EP2[s * 32 + li];         // expG, 4 dims
    const uint2 pu = EP2[s * 32 + 16 + li];    // P, 4 dims
    const float4 eg = Eg4[t * 16 + li];        // exp(Eg+Bg), fp32 (hot)

    const float2 g01 = __half22float2(*(const __half2*)&gu.x);
    const float2 g23 = __half22float2(*(const __half2*)&gu.y);
    const float2 p01 = __half22float2(*(const __half2*)&pu.x);
    const float2 p23 = __half22float2(*(const __half2*)&pu.y);

    const float ex0 = g01.x * eg.x;
    const float ex1 = g01.y * eg.y;
    const float ex2 = g23.x * eg.z;
    const float ex3 = g23.y * eg.w;

    den.x += ex0; den.y += ex1; den.z += ex2; den.w += ex3;
    num.x += p01.x * ex0;
    num.y += p01.y * ex1;
    num.z += p23.x * ex2;
    num.w += p23.y * ex3;
}

__global__ void __launch_bounds__(256) consume_kernel(float4* __restrict__ out, int N)
{
    const int gw = (blockIdx.x * blockDim.x + threadIdx.x) >> 5;  // receiver
    if (gw >= N) return;
    const int lane = threadIdx.x & 31;
    const int half = lane >> 4;
    const int li   = lane & 15;

    const int start = g_start[gw];
    const int cnt   = g_cnt[gw];
    const int mid   = start + ((cnt + 1) >> 1);
    const int lo    = half ? mid : start;
    const int hi    = half ? (start + cnt) : mid;

    const uint2*  EP2 = (const uint2*)g_EP;
    const float4* Eg4 = (const float4*)g_expEgb;

    float4 num = make_float4(0.f, 0.f, 0.f, 0.f);
    float4 den = make_float4(0.f, 0.f, 0.f, 0.f);

    int i = lo;
    for (; i + 1 < hi; i += 2) {
        const unsigned e0 = g_edge[i];
        const unsigned e1 = g_edge[i + 1];
        edge_accum(e0, li, EP2, Eg4, num, den);
        edge_accum(e1, li, EP2, Eg4, num, den);
    }
    if (i < hi) {
        edge_accum(g_edge[i], li, EP2, Eg4, num, den);
    }

    // combine the two half-warps (same li)
    num.x += __shfl_xor_sync(0xffffffffu, num.x, 16);
    num.y += __shfl_xor_sync(0xffffffffu, num.y, 16);
    num.z += __shfl_xor_sync(0xffffffffu, num.z, 16);
    num.w += __shfl_xor_sync(0xffffffffu, num.w, 16);
    den.x += __shfl_xor_sync(0xffffffffu, den.x, 16);
    den.y += __shfl_xor_sync(0xffffffffu, den.y, 16);
    den.z += __shfl_xor_sync(0xffffffffu, den.z, 16);
    den.w += __shfl_xor_sync(0xffffffffu, den.w, 16);

    if (half == 0) {
        float4 v;
        v.x = (den.x > 0.f) ? num.x / den.x : 0.f;
        v.y = (den.y > 0.f) ? num.y / den.y : 0.f;
        v.z = (den.z > 0.f) ? num.z / den.z : 0.f;
        v.w = (den.w > 0.f) ? num.w / den.w : 0.f;
        out[gw * 16 + li] = v;
    }
}

extern "C" void kernel_launch(void* const* d_in, const int* in_sizes, int n_in,
                              void* d_out, int out_size)
{
    const float* node_codes = (const float*)d_in[0];
    const float* Vp         = (const float*)d_in[1];
    const float* Vg         = (const float*)d_in[2];
    const float* Eg         = (const float*)d_in[3];
    const float* Bm         = (const float*)d_in[4];
    const float* Bg         = (const float*)d_in[5];
    const int*   snd        = (const int*)d_in[6];
    const int*   rcv        = (const int*)d_in[7];
    const int*   typ        = (const int*)d_in[8];

    const int N = in_sizes[0] / DD;
    const int E = in_sizes[6];

    const int SMEM_B = 2 * 8 * 8 * 2 * 32 * 8;   // 65536 bytes
    cudaFuncSetAttribute(node_kernel,
                         cudaFuncAttributeMaxDynamicSharedMemorySize, SMEM_B);

    const int prep_n = (N > NREL * DD) ? N : NREL * DD;
    prep_kernel<<<(prep_n + 255) / 256, 256>>>(Eg, Bg, N);

    {
        const int nwarp = (N + 15) / 16;
        const int blocks = (nwarp + 7) / 8;
        node_kernel<<<blocks, 256, SMEM_B>>>(node_codes, Vp, Vg, Bm, N);
    }

    hist_kernel<<<(E + 255) / 256, 256>>>(rcv, E);

    const int nblk = (N + 1023) / 1024;
    scan1_kernel<<<nblk, 1024>>>(N);
    scan2_kernel<<<1, 128>>>(nblk);
    scan3_kernel<<<(N + 255) / 256, 256>>>(N);

    scatter_kernel<<<(E + 255) / 256, 256>>>(snd, rcv, typ, E);

    {
        const long long threads = (long long)N * 32;
        const int blocks = (int)((threads + 255) / 256);
        consume_kernel<<<blocks, 256>>>((float4*)d_out, N);
    }
}

// round 6
// speedup vs baseline: 1.6620x; 1.0599x over previous
#include <cuda_runtime.h>
#include <cuda_fp16.h>

#define DD   64
#define MAXN 100000
#define MAXE 1600000
#define NREL 201

// Scratch (allocation-free rule: __device__ globals)
// g_EP: per node 128 halves, interleaved per 4-dim lane: [expG x4 | P x4]
// lane li (0..15) owns dims 4li..4li+3 -> one uint4 per (node, lane).
__device__ __half    g_EP[MAXN * 128];
__device__ float     g_expEgb[NREL * DD];   // exp(E_gate + B_gate_pre)
__device__ int       g_cnt[MAXN];
__device__ int       g_incl[MAXN];
__device__ int       g_btot[128];
__device__ int       g_start[MAXN];
__device__ int       g_rank[MAXE];          // within-receiver rank of each edge
__device__ unsigned  g_edge[MAXE];          // sender | (type<<17), grouped by receiver

// ---------------------------------------------------------------------------
// tf32 helpers
// ---------------------------------------------------------------------------
__device__ __forceinline__ unsigned f2tf32(float x) {
    unsigned r;
    asm("cvt.rna.tf32.f32 %0, %1;" : "=r"(r) : "f"(x));
    return r;
}

#define MMA_TF32(d0,d1,d2,d3,a0,a1,a2,a3,b0,b1) \
    asm volatile("mma.sync.aligned.m16n8k8.row.col.f32.tf32.tf32.f32 " \
        "{%0,%1,%2,%3}, {%4,%5,%6,%7}, {%8,%9}, {%0,%1,%2,%3};" \
        : "+f"(d0), "+f"(d1), "+f"(d2), "+f"(d3) \
        : "r"(a0), "r"(a1), "r"(a2), "r"(a3), "r"(b0), "r"(b1))

// ---------------------------------------------------------------------------
// Prep: zero histogram; expEgb = exp(E_gate + B_gate_pre)
// ---------------------------------------------------------------------------
__global__ void __launch_bounds__(256) prep_kernel(
    const float* __restrict__ Eg, const float* __restrict__ Bg, int N)
{
    const int i = blockIdx.x * blockDim.x + threadIdx.x;
    if (i < N) g_cnt[i] = 0;
    if (i < NREL * DD) g_expEgb[i] = __expf(Eg[i] + Bg[i & (DD - 1)]);
}

// ---------------------------------------------------------------------------
// Node kernel (tensor core): expG = exp(X @ Vg), P = relu(X @ Vp + Bm).
// mma.sync.m16n8k8 tf32, 3-term split for fp32-grade accuracy.
// Output layout per node: lane li owns halves [li*8 .. li*8+7] =
// expG dims 4li..4li+3 at +0..3, P dims 4li..4li+3 at +4..7.
// ---------------------------------------------------------------------------
__global__ void __launch_bounds__(256) node_kernel(
    const float* __restrict__ X,
    const float* __restrict__ Vp,
    const float* __restrict__ Vg,
    const float* __restrict__ Bm,
    int N)
{
    extern __shared__ unsigned sB[];   // 2*8*8*2*32 uint2 = 64KB
    const int tid = threadIdx.x;

    // Build weight fragments (mat0 = Vg -> expG, mat1 = Vp -> P)
    for (int idx = tid; idx < 2 * 8 * 8 * 2 * 32; idx += 256) {
        const int lane = idx & 31;
        const int hl   = (idx >> 5) & 1;
        const int k    = (idx >> 6) & 7;
        const int n    = (idx >> 9) & 7;
        const int mat  = (idx >> 12) & 1;
        const float* __restrict__ V = (mat == 0) ? Vg : Vp;
        const int t = lane & 3, g = lane >> 2;
        const float v0 = V[(k * 8 + t) * DD + n * 8 + g];
        const float v1 = V[(k * 8 + t + 4) * DD + n * 8 + g];
        unsigned o0, o1;
        if (hl == 0) {
            o0 = f2tf32(v0);
            o1 = f2tf32(v1);
        } else {
            const unsigned h0 = f2tf32(v0), h1 = f2tf32(v1);
            o0 = f2tf32(v0 - __uint_as_float(h0));
            o1 = f2tf32(v1 - __uint_as_float(h1));
        }
        ((uint2*)sB)[idx] = make_uint2(o0, o1);
    }
    __syncthreads();

    const int warp = tid >> 5;
    const int lane = tid & 31;
    const int m0   = (blockIdx.x * 8 + warp) * 16;
    if (m0 >= N) return;

    const int t = lane & 3, g = lane >> 2;
    const int r0 = m0 + g;
    const int r1 = m0 + g + 8;
    const bool r0ok = r0 < N;
    const bool r1ok = r1 < N;

    unsigned Ahi[8][4], Alo[8][4];
    const float* __restrict__ xr0 = X + (size_t)r0 * DD;
    const float* __restrict__ xr1 = X + (size_t)r1 * DD;
    #pragma unroll
    for (int k = 0; k < 8; k++) {
        float x0 = r0ok ? __ldg(&xr0[k * 8 + t])     : 0.f;
        float x1 = r1ok ? __ldg(&xr1[k * 8 + t])     : 0.f;
        float x2 = r0ok ? __ldg(&xr0[k * 8 + t + 4]) : 0.f;
        float x3 = r1ok ? __ldg(&xr1[k * 8 + t + 4]) : 0.f;
        Ahi[k][0] = f2tf32(x0); Alo[k][0] = f2tf32(x0 - __uint_as_float(Ahi[k][0]));
        Ahi[k][1] = f2tf32(x1); Alo[k][1] = f2tf32(x1 - __uint_as_float(Ahi[k][1]));
        Ahi[k][2] = f2tf32(x2); Alo[k][2] = f2tf32(x2 - __uint_as_float(Ahi[k][2]));
        Ahi[k][3] = f2tf32(x3); Alo[k][3] = f2tf32(x3 - __uint_as_float(Ahi[k][3]));
    }

    const uint2* __restrict__ sB2 = (const uint2*)sB;

    #pragma unroll
    for (int mat = 0; mat < 2; mat++) {
        #pragma unroll
        for (int n = 0; n < 8; n++) {
            float d0 = 0.f, d1 = 0.f, d2 = 0.f, d3 = 0.f;
            #pragma unroll
            for (int k = 0; k < 8; k++) {
                const int base = (((mat * 8 + n) * 8 + k) * 2) * 32 + lane;
                const uint2 bh = sB2[base];
                const uint2 bl = sB2[base + 32];
                MMA_TF32(d0, d1, d2, d3,
                         Ahi[k][0], Ahi[k][1], Ahi[k][2], Ahi[k][3], bh.x, bh.y);
                MMA_TF32(d0, d1, d2, d3,
                         Ahi[k][0], Ahi[k][1], Ahi[k][2], Ahi[k][3], bl.x, bl.y);
                MMA_TF32(d0, d1, d2, d3,
                         Alo[k][0], Alo[k][1], Alo[k][2], Alo[k][3], bh.x, bh.y);
            }
            // columns c0, c0+1 (c0 even)
            const int c0 = n * 8 + 2 * t;
            const int li = c0 >> 2;
            // interleaved offsets (in halves)
            const int offG = li * 8 + (c0 & 3);
            const int offP = li * 8 + 4 + (c0 & 3);
            if (mat == 0) {
                if (r0ok) *(__half2*)&g_EP[(size_t)r0 * 128 + offG] =
                    __floats2half2_rn(__expf(d0), __expf(d1));
                if (r1ok) *(__half2*)&g_EP[(size_t)r1 * 128 + offG] =
                    __floats2half2_rn(__expf(d2), __expf(d3));
            } else {
                const float b0v = __ldg(&Bm[c0]);
                const float b1v = __ldg(&Bm[c0 + 1]);
                if (r0ok) *(__half2*)&g_EP[(size_t)r0 * 128 + offP] =
                    __floats2half2_rn(fmaxf(d0 + b0v, 0.f), fmaxf(d1 + b1v, 0.f));
                if (r1ok) *(__half2*)&g_EP[(size_t)r1 * 128 + offP] =
                    __floats2half2_rn(fmaxf(d2 + b0v, 0.f), fmaxf(d3 + b1v, 0.f));
            }
        }
    }
}

// ---------------------------------------------------------------------------
// CSR build: hist (atomic rank) -> scan -> scatter (NO second atomic pass)
// ---------------------------------------------------------------------------
__global__ void __launch_bounds__(256) hist_kernel(const int* __restrict__ rcv, int E)
{
    const int e = blockIdx.x * blockDim.x + threadIdx.x;
    if (e < E) g_rank[e] = atomicAdd(&g_cnt[rcv[e]], 1);
}

__global__ void __launch_bounds__(1024) scan1_kernel(int N)
{
    __shared__ int wsum[32];
    const int i    = blockIdx.x * 1024 + threadIdx.x;
    const int lane = threadIdx.x & 31;
    const int w    = threadIdx.x >> 5;

    int s = (i < N) ? g_cnt[i] : 0;
    #pragma unroll
    for (int d = 1; d < 32; d <<= 1) {
        int tv = __shfl_up_sync(0xffffffffu, s, d);
        if (lane >= d) s += tv;
    }
    if (lane == 31) wsum[w] = s;
    __syncthreads();
    if (w == 0) {
        int ws = wsum[lane];
        #pragma unroll
        for (int d = 1; d < 32; d <<= 1) {
            int tv = __shfl_up_sync(0xffffffffu, ws, d);
            if (lane >= d) ws += tv;
        }
        wsum[lane] = ws;
    }
    __syncthreads();
    if (w > 0) s += wsum[w - 1];
    if (i < N) g_incl[i] = s;
    if (threadIdx.x == 1023) g_btot[blockIdx.x] = s;
}

// scan2+scan3 merged: every block redundantly prefix-scans the (<=128) block
// totals in smem, then computes row starts for its 256 indices.
__global__ void __launch_bounds__(256) scan23_kernel(int N, int nblk)
{
    __shared__ int sm[128];
    if (threadIdx.x < 128)
        sm[threadIdx.x] = (threadIdx.x < nblk) ? g_btot[threadIdx.x] : 0;
    __syncthreads();
    #pragma unroll
    for (int d = 1; d < 128; d <<= 1) {
        int t = 0;
        if (threadIdx.x < 128 && threadIdx.x >= d) t = sm[threadIdx.x - d];
        __syncthreads();
        if (threadIdx.x < 128) sm[threadIdx.x] += t;
        __syncthreads();
    }
    const int i = blockIdx.x * blockDim.x + threadIdx.x;
    if (i < N) {
        const int blk = i >> 10;
        const int boff = (blk == 0) ? 0 : sm[blk - 1];
        g_start[i] = g_incl[i] - g_cnt[i] + boff;
    }
}

__global__ void __launch_bounds__(256) scatter_kernel(
    const int* __restrict__ snd, const int* __restrict__ rcv,
    const int* __restrict__ typ, int E)
{
    const int e = blockIdx.x * blockDim.x + threadIdx.x;
    if (e < E) {
        const int pos = g_start[rcv[e]] + g_rank[e];
        g_edge[pos] = (unsigned)snd[e] | ((unsigned)typ[e] << 17);
    }
}

// ---------------------------------------------------------------------------
// Consume: one warp per receiver; half-warps take contiguous halves of the
// edge range; 16 lanes cover D=64 (4 dims/lane). One LDG.128 per edge per
// lane (interleaved expG|P), fp32 accumulate, 4-edge unroll for MLP.
// ---------------------------------------------------------------------------
__device__ __forceinline__ void edge_accum(
    unsigned e, int li, const uint4* __restrict__ EP4,
    const float4* __restrict__ Eg4, float4& num, float4& den)
{
    const int s = (int)(e & 0x1FFFFu);
    const int t = (int)(e >> 17);

    const uint4  v  = EP4[s * 16 + li];        // expG x4 | P x4 (fp16)
    const float4 eg = Eg4[t * 16 + li];        // exp(Eg+Bg), fp32 (hot)

    const float2 g01 = __half22float2(*(const __half2*)&v.x);
    const float2 g23 = __half22float2(*(const __half2*)&v.y);
    const float2 p01 = __half22float2(*(const __half2*)&v.z);
    const float2 p23 = __half22float2(*(const __half2*)&v.w);

    const float ex0 = g01.x * eg.x;
    const float ex1 = g01.y * eg.y;
    const float ex2 = g23.x * eg.z;
    const float ex3 = g23.y * eg.w;

    den.x += ex0; den.y += ex1; den.z += ex2; den.w += ex3;
    num.x += p01.x * ex0;
    num.y += p01.y * ex1;
    num.z += p23.x * ex2;
    num.w += p23.y * ex3;
}

__global__ void __launch_bounds__(256) consume_kernel(float4* __restrict__ out, int N)
{
    const int gw = (blockIdx.x * blockDim.x + threadIdx.x) >> 5;  // receiver
    if (gw >= N) return;
    const int lane = threadIdx.x & 31;
    const int half = lane >> 4;
    const int li   = lane & 15;

    const int start = g_start[gw];
    const int cnt   = g_cnt[gw];
    const int mid   = start + ((cnt + 1) >> 1);
    const int lo    = half ? mid : start;
    const int hi    = half ? (start + cnt) : mid;

    const uint4*  EP4 = (const uint4*)g_EP;
    const float4* Eg4 = (const float4*)g_expEgb;

    float4 num = make_float4(0.f, 0.f, 0.f, 0.f);
    float4 den = make_float4(0.f, 0.f, 0.f, 0.f);

    int i = lo;
    for (; i + 3 < hi; i += 4) {
        const unsigned e0 = g_edge[i];
        const unsigned e1 = g_edge[i + 1];
        const unsigned e2 = g_edge[i + 2];
        const unsigned e3 = g_edge[i + 3];
        edge_accum(e0, li, EP4, Eg4, num, den);
        edge_accum(e1, li, EP4, Eg4, num, den);
        edge_accum(e2, li, EP4, Eg4, num, den);
        edge_accum(e3, li, EP4, Eg4, num, den);
    }
    for (; i < hi; i++) {
        edge_accum(g_edge[i], li, EP4, Eg4, num, den);
    }

    // combine the two half-warps (same li)
    num.x += __shfl_xor_sync(0xffffffffu, num.x, 16);
    num.y += __shfl_xor_sync(0xffffffffu, num.y, 16);
    num.z += __shfl_xor_sync(0xffffffffu, num.z, 16);
    num.w += __shfl_xor_sync(0xffffffffu, num.w, 16);
    den.x += __shfl_xor_sync(0xffffffffu, den.x, 16);
    den.y += __shfl_xor_sync(0xffffffffu, den.y, 16);
    den.z += __shfl_xor_sync(0xffffffffu, den.z, 16);
    den.w += __shfl_xor_sync(0xffffffffu, den.w, 16);

    if (half == 0) {
        float4 v;
        v.x = (den.x > 0.f) ? num.x / den.x : 0.f;
        v.y = (den.y > 0.f) ? num.y / den.y : 0.f;
        v.z = (den.z > 0.f) ? num.z / den.z : 0.f;
        v.w = (den.w > 0.f) ? num.w / den.w : 0.f;
        out[gw * 16 + li] = v;
    }
}

extern "C" void kernel_launch(void* const* d_in, const int* in_sizes, int n_in,
                              void* d_out, int out_size)
{
    const float* node_codes = (const float*)d_in[0];
    const float* Vp         = (const float*)d_in[1];
    const float* Vg         = (const float*)d_in[2];
    const float* Eg         = (const float*)d_in[3];
    const float* Bm         = (const float*)d_in[4];
    const float* Bg         = (const float*)d_in[5];
    const int*   snd        = (const int*)d_in[6];
    const int*   rcv        = (const int*)d_in[7];
    const int*   typ        = (const int*)d_in[8];

    const int N = in_sizes[0] / DD;
    const int E = in_sizes[6];

    const int SMEM_B = 2 * 8 * 8 * 2 * 32 * 8;   // 65536 bytes
    cudaFuncSetAttribute(node_kernel,
                         cudaFuncAttributeMaxDynamicSharedMemorySize, SMEM_B);

    const int prep_n = (N > NREL * DD) ? N : NREL * DD;
    prep_kernel<<<(prep_n + 255) / 256, 256>>>(Eg, Bg, N);

    {
        const int nwarp = (N + 15) / 16;
        const int blocks = (nwarp + 7) / 8;
        node_kernel<<<blocks, 256, SMEM_B>>>(node_codes, Vp, Vg, Bm, N);
    }

    hist_kernel<<<(E + 255) / 256, 256>>>(rcv, E);

    const int nblk = (N + 1023) / 1024;
    scan1_kernel<<<nblk, 1024>>>(N);
    scan23_kernel<<<(N + 255) / 256, 256>>>(N, nblk);

    scatter_kernel<<<(E + 255) / 256, 256>>>(snd, rcv, typ, E);

    {
        const long long threads = (long long)N * 32;
        const int blocks = (int)((threads + 255) / 256);
        consume_kernel<<<blocks, 256>>>((float4*)d_out, N);
    }
}

// round 7
// speedup vs baseline: 1.6667x; 1.0028x over previous
#include <cuda_runtime.h>
#include <cuda_fp16.h>

#define DD   64
#define MAXN 100000
#define MAXE 1600000
#define NREL 201

// Scratch (allocation-free rule: __device__ globals)
// g_EP: per node 128 halves, interleaved per 4-dim lane: [expG x4 | P x4]
__device__ __half    g_EP[MAXN * 128];
__device__ float     g_expEgb[NREL * DD];   // exp(E_gate + B_gate_pre)
__device__ int       g_cnt[MAXN];
__device__ int       g_incl[MAXN];
__device__ int       g_btot[128];
__device__ int       g_start[MAXN];
__device__ int       g_rank[MAXE];          // within-receiver rank of each edge
__device__ unsigned  g_edge[MAXE];          // sender | (type<<17), grouped by receiver

// ---------------------------------------------------------------------------
// tf32 helpers
// ---------------------------------------------------------------------------
__device__ __forceinline__ unsigned f2tf32(float x) {
    unsigned r;
    asm("cvt.rna.tf32.f32 %0, %1;" : "=r"(r) : "f"(x));
    return r;
}

#define MMA_TF32(d0,d1,d2,d3,a0,a1,a2,a3,b0,b1) \
    asm volatile("mma.sync.aligned.m16n8k8.row.col.f32.tf32.tf32.f32 " \
        "{%0,%1,%2,%3}, {%4,%5,%6,%7}, {%8,%9}, {%0,%1,%2,%3};" \
        : "+f"(d0), "+f"(d1), "+f"(d2), "+f"(d3) \
        : "r"(a0), "r"(a1), "r"(a2), "r"(a3), "r"(b0), "r"(b1))

// ---------------------------------------------------------------------------
// Fused front kernel. Block roles by blockIdx.x:
//   [0, nodeBlocks)              : tensor-core node GEMMs -> g_EP
//   [nodeBlocks, nodeBlocks+eb)  : expEgb = exp(E_gate + B_gate_pre)
//   [nodeBlocks+eb, ...)         : histogram (rank via atomic), 4 edges/thread
// node and hist are independent; co-scheduling overlaps them on the SMs.
// ---------------------------------------------------------------------------
__global__ void __launch_bounds__(256) fused_front_kernel(
    const float* __restrict__ X,
    const float* __restrict__ Vp,
    const float* __restrict__ Vg,
    const float* __restrict__ Bm,
    const float* __restrict__ Eg,
    const float* __restrict__ Bg,
    const int*   __restrict__ rcv,
    int N, int E, int nodeBlocks, int egbBlocks)
{
    extern __shared__ unsigned sB[];   // node role: 2*8*8*2*32 uint2 = 64KB
    const int tid = threadIdx.x;
    const int bid = blockIdx.x;

    if (bid >= nodeBlocks) {
        if (bid < nodeBlocks + egbBlocks) {
            // ---- expEgb role ----
            const int i = (bid - nodeBlocks) * 256 + tid;
            if (i < NREL * DD) g_expEgb[i] = __expf(Eg[i] + Bg[i & (DD - 1)]);
        } else {
            // ---- hist role: 4 edges per thread, coalesced stride-256 ----
            const int chunk = (bid - nodeBlocks - egbBlocks) * 1024;
            #pragma unroll
            for (int j = 0; j < 4; j++) {
                const int e = chunk + j * 256 + tid;
                if (e < E) g_rank[e] = atomicAdd(&g_cnt[rcv[e]], 1);
            }
        }
        return;
    }

    // ---- node role ----
    // Build weight fragments (mat0 = Vg -> expG, mat1 = Vp -> P)
    for (int idx = tid; idx < 2 * 8 * 8 * 2 * 32; idx += 256) {
        const int lane = idx & 31;
        const int hl   = (idx >> 5) & 1;
        const int k    = (idx >> 6) & 7;
        const int n    = (idx >> 9) & 7;
        const int mat  = (idx >> 12) & 1;
        const float* __restrict__ V = (mat == 0) ? Vg : Vp;
        const int t = lane & 3, g = lane >> 2;
        const float v0 = V[(k * 8 + t) * DD + n * 8 + g];
        const float v1 = V[(k * 8 + t + 4) * DD + n * 8 + g];
        unsigned o0, o1;
        if (hl == 0) {
            o0 = f2tf32(v0);
            o1 = f2tf32(v1);
        } else {
            const unsigned h0 = f2tf32(v0), h1 = f2tf32(v1);
            o0 = f2tf32(v0 - __uint_as_float(h0));
            o1 = f2tf32(v1 - __uint_as_float(h1));
        }
        ((uint2*)sB)[idx] = make_uint2(o0, o1);
    }
    __syncthreads();

    const int warp = tid >> 5;
    const int lane = tid & 31;
    const int m0   = (bid * 8 + warp) * 16;
    if (m0 >= N) return;

    const int t = lane & 3, g = lane >> 2;
    const int r0 = m0 + g;
    const int r1 = m0 + g + 8;
    const bool r0ok = r0 < N;
    const bool r1ok = r1 < N;

    unsigned Ahi[8][4], Alo[8][4];
    const float* __restrict__ xr0 = X + (size_t)r0 * DD;
    const float* __restrict__ xr1 = X + (size_t)r1 * DD;
    #pragma unroll
    for (int k = 0; k < 8; k++) {
        float x0 = r0ok ? __ldg(&xr0[k * 8 + t])     : 0.f;
        float x1 = r1ok ? __ldg(&xr1[k * 8 + t])     : 0.f;
        float x2 = r0ok ? __ldg(&xr0[k * 8 + t + 4]) : 0.f;
        float x3 = r1ok ? __ldg(&xr1[k * 8 + t + 4]) : 0.f;
        Ahi[k][0] = f2tf32(x0); Alo[k][0] = f2tf32(x0 - __uint_as_float(Ahi[k][0]));
        Ahi[k][1] = f2tf32(x1); Alo[k][1] = f2tf32(x1 - __uint_as_float(Ahi[k][1]));
        Ahi[k][2] = f2tf32(x2); Alo[k][2] = f2tf32(x2 - __uint_as_float(Ahi[k][2]));
        Ahi[k][3] = f2tf32(x3); Alo[k][3] = f2tf32(x3 - __uint_as_float(Ahi[k][3]));
    }

    const uint2* __restrict__ sB2 = (const uint2*)sB;

    #pragma unroll
    for (int mat = 0; mat < 2; mat++) {
        #pragma unroll
        for (int n = 0; n < 8; n++) {
            float d0 = 0.f, d1 = 0.f, d2 = 0.f, d3 = 0.f;
            #pragma unroll
            for (int k = 0; k < 8; k++) {
                const int base = (((mat * 8 + n) * 8 + k) * 2) * 32 + lane;
                const uint2 bh = sB2[base];
                const uint2 bl = sB2[base + 32];
                MMA_TF32(d0, d1, d2, d3,
                         Ahi[k][0], Ahi[k][1], Ahi[k][2], Ahi[k][3], bh.x, bh.y);
                MMA_TF32(d0, d1, d2, d3,
                         Ahi[k][0], Ahi[k][1], Ahi[k][2], Ahi[k][3], bl.x, bl.y);
                MMA_TF32(d0, d1, d2, d3,
                         Alo[k][0], Alo[k][1], Alo[k][2], Alo[k][3], bh.x, bh.y);
            }
            const int c0 = n * 8 + 2 * t;      // even column
            const int li = c0 >> 2;
            const int offG = li * 8 + (c0 & 3);
            const int offP = li * 8 + 4 + (c0 & 3);
            if (mat == 0) {
                if (r0ok) *(__half2*)&g_EP[(size_t)r0 * 128 + offG] =
                    __floats2half2_rn(__expf(d0), __expf(d1));
                if (r1ok) *(__half2*)&g_EP[(size_t)r1 * 128 + offG] =
                    __floats2half2_rn(__expf(d2), __expf(d3));
            } else {
                const float b0v = __ldg(&Bm[c0]);
                const float b1v = __ldg(&Bm[c0 + 1]);
                if (r0ok) *(__half2*)&g_EP[(size_t)r0 * 128 + offP] =
                    __floats2half2_rn(fmaxf(d0 + b0v, 0.f), fmaxf(d1 + b1v, 0.f));
                if (r1ok) *(__half2*)&g_EP[(size_t)r1 * 128 + offP] =
                    __floats2half2_rn(fmaxf(d2 + b0v, 0.f), fmaxf(d3 + b1v, 0.f));
            }
        }
    }
}

// ---------------------------------------------------------------------------
// Scan (two kernels), then scatter via saved ranks (no second atomic pass)
// ---------------------------------------------------------------------------
__global__ void __launch_bounds__(1024) scan1_kernel(int N)
{
    __shared__ int wsum[32];
    const int i    = blockIdx.x * 1024 + threadIdx.x;
    const int lane = threadIdx.x & 31;
    const int w    = threadIdx.x >> 5;

    int s = (i < N) ? g_cnt[i] : 0;
    #pragma unroll
    for (int d = 1; d < 32; d <<= 1) {
        int tv = __shfl_up_sync(0xffffffffu, s, d);
        if (lane >= d) s += tv;
    }
    if (lane == 31) wsum[w] = s;
    __syncthreads();
    if (w == 0) {
        int ws = wsum[lane];
        #pragma unroll
        for (int d = 1; d < 32; d <<= 1) {
            int tv = __shfl_up_sync(0xffffffffu, ws, d);
            if (lane >= d) ws += tv;
        }
        wsum[lane] = ws;
    }
    __syncthreads();
    if (w > 0) s += wsum[w - 1];
    if (i < N) g_incl[i] = s;
    if (threadIdx.x == 1023) g_btot[blockIdx.x] = s;
}

__global__ void __launch_bounds__(256) scan23_kernel(int N, int nblk)
{
    __shared__ int sm[128];
    if (threadIdx.x < 128)
        sm[threadIdx.x] = (threadIdx.x < nblk) ? g_btot[threadIdx.x] : 0;
    __syncthreads();
    #pragma unroll
    for (int d = 1; d < 128; d <<= 1) {
        int t = 0;
        if (threadIdx.x < 128 && threadIdx.x >= d) t = sm[threadIdx.x - d];
        __syncthreads();
        if (threadIdx.x < 128) sm[threadIdx.x] += t;
        __syncthreads();
    }
    const int i = blockIdx.x * blockDim.x + threadIdx.x;
    if (i < N) {
        const int blk = i >> 10;
        const int boff = (blk == 0) ? 0 : sm[blk - 1];
        g_start[i] = g_incl[i] - g_cnt[i] + boff;
    }
}

__global__ void __launch_bounds__(256) scatter_kernel(
    const int* __restrict__ snd, const int* __restrict__ rcv,
    const int* __restrict__ typ, int E)
{
    const int base = blockIdx.x * 1024;
    #pragma unroll
    for (int j = 0; j < 4; j++) {
        const int e = base + j * 256 + threadIdx.x;
        if (e < E) {
            const int pos = g_start[rcv[e]] + g_rank[e];
            g_edge[pos] = (unsigned)snd[e] | ((unsigned)typ[e] << 17);
        }
    }
}

// ---------------------------------------------------------------------------
// Consume: one warp per receiver; half-warps take contiguous halves of the
// edge range; 16 lanes cover D=64 (4 dims/lane). One LDG.128 per edge per
// lane (interleaved expG|P), fp32 accumulate, 4-edge unroll for MLP.
// ---------------------------------------------------------------------------
__device__ __forceinline__ void edge_accum(
    unsigned e, int li, const uint4* __restrict__ EP4,
    const float4* __restrict__ Eg4, float4& num, float4& den)
{
    const int s = (int)(e & 0x1FFFFu);
    const int t = (int)(e >> 17);

    const uint4  v  = EP4[s * 16 + li];        // expG x4 | P x4 (fp16)
    const float4 eg = Eg4[t * 16 + li];        // exp(Eg+Bg), fp32 (hot)

    const float2 g01 = __half22float2(*(const __half2*)&v.x);
    const float2 g23 = __half22float2(*(const __half2*)&v.y);
    const float2 p01 = __half22float2(*(const __half2*)&v.z);
    const float2 p23 = __half22float2(*(const __half2*)&v.w);

    const float ex0 = g01.x * eg.x;
    const float ex1 = g01.y * eg.y;
    const float ex2 = g23.x * eg.z;
    const float ex3 = g23.y * eg.w;

    den.x += ex0; den.y += ex1; den.z += ex2; den.w += ex3;
    num.x += p01.x * ex0;
    num.y += p01.y * ex1;
    num.z += p23.x * ex2;
    num.w += p23.y * ex3;
}

__global__ void __launch_bounds__(256) consume_kernel(float4* __restrict__ out, int N)
{
    const int gw = (blockIdx.x * blockDim.x + threadIdx.x) >> 5;  // receiver
    if (gw >= N) return;
    const int lane = threadIdx.x & 31;
    const int half = lane >> 4;
    const int li   = lane & 15;

    const int start = g_start[gw];
    const int cnt   = g_cnt[gw];
    const int mid   = start + ((cnt + 1) >> 1);
    const int lo    = half ? mid : start;
    const int hi    = half ? (start + cnt) : mid;

    const uint4*  EP4 = (const uint4*)g_EP;
    const float4* Eg4 = (const float4*)g_expEgb;

    float4 num = make_float4(0.f, 0.f, 0.f, 0.f);
    float4 den = make_float4(0.f, 0.f, 0.f, 0.f);

    int i = lo;
    for (; i + 3 < hi; i += 4) {
        const unsigned e0 = g_edge[i];
        const unsigned e1 = g_edge[i + 1];
        const unsigned e2 = g_edge[i + 2];
        const unsigned e3 = g_edge[i + 3];
        edge_accum(e0, li, EP4, Eg4, num, den);
        edge_accum(e1, li, EP4, Eg4, num, den);
        edge_accum(e2, li, EP4, Eg4, num, den);
        edge_accum(e3, li, EP4, Eg4, num, den);
    }
    for (; i < hi; i++) {
        edge_accum(g_edge[i], li, EP4, Eg4, num, den);
    }

    num.x += __shfl_xor_sync(0xffffffffu, num.x, 16);
    num.y += __shfl_xor_sync(0xffffffffu, num.y, 16);
    num.z += __shfl_xor_sync(0xffffffffu, num.z, 16);
    num.w += __shfl_xor_sync(0xffffffffu, num.w, 16);
    den.x += __shfl_xor_sync(0xffffffffu, den.x, 16);
    den.y += __shfl_xor_sync(0xffffffffu, den.y, 16);
    den.z += __shfl_xor_sync(0xffffffffu, den.z, 16);
    den.w += __shfl_xor_sync(0xffffffffu, den.w, 16);

    if (half == 0) {
        float4 v;
        v.x = (den.x > 0.f) ? num.x / den.x : 0.f;
        v.y = (den.y > 0.f) ? num.y / den.y : 0.f;
        v.z = (den.z > 0.f) ? num.z / den.z : 0.f;
        v.w = (den.w > 0.f) ? num.w / den.w : 0.f;
        out[gw * 16 + li] = v;
    }
}

extern "C" void kernel_launch(void* const* d_in, const int* in_sizes, int n_in,
                              void* d_out, int out_size)
{
    const float* node_codes = (const float*)d_in[0];
    const float* Vp         = (const float*)d_in[1];
    const float* Vg         = (const float*)d_in[2];
    const float* Eg         = (const float*)d_in[3];
    const float* Bm         = (const float*)d_in[4];
    const float* Bg         = (const float*)d_in[5];
    const int*   snd        = (const int*)d_in[6];
    const int*   rcv        = (const int*)d_in[7];
    const int*   typ        = (const int*)d_in[8];

    const int N = in_sizes[0] / DD;
    const int E = in_sizes[6];

    const int SMEM_B = 2 * 8 * 8 * 2 * 32 * 8;   // 65536 bytes
    cudaFuncSetAttribute(fused_front_kernel,
                         cudaFuncAttributeMaxDynamicSharedMemorySize, SMEM_B);

    void* cntp = nullptr;
    cudaGetSymbolAddress(&cntp, g_cnt);
    cudaMemsetAsync(cntp, 0, (size_t)N * sizeof(int));

    {
        const int nodeBlocks = ((N + 15) / 16 + 7) / 8;
        const int egbBlocks  = (NREL * DD + 255) / 256;
        const int histBlocks = (E + 1023) / 1024;
        const int total = nodeBlocks + egbBlocks + histBlocks;
        fused_front_kernel<<<total, 256, SMEM_B>>>(
            node_codes, Vp, Vg, Bm, Eg, Bg, rcv, N, E, nodeBlocks, egbBlocks);
    }

    const int nblk = (N + 1023) / 1024;
    scan1_kernel<<<nblk, 1024>>>(N);
    scan23_kernel<<<(N + 255) / 256, 256>>>(N, nblk);

    scatter_kernel<<<(E + 1023) / 1024, 256>>>(snd, rcv, typ, E);

    {
        const long long threads = (long long)N * 32;
        const int blocks = (int)((threads + 255) / 256);
        consume_kernel<<<blocks, 256>>>((float4*)d_out, N);
    }
}